// round 1
// baseline (speedup 1.0000x reference)
#include <cuda_runtime.h>
#include <cuda_bf16.h>
#include <math.h>

// Problem constants
#define BATCH 64
#define TT    48
#define C_IN  64
#define HH    15
#define WW    15
#define PIX   225      // 15*15
#define HID   128
#define SH    17       // padded smem tile edge (15 + 2 halo)

#define SLAB (BATCH * HID * PIX)   // one state buffer: 64*128*225 = 1,843,200 floats

// State scratch (static device globals — no allocation APIs)
__device__ float g_h1[2 * SLAB];
__device__ float g_c1[SLAB];
__device__ float g_h2[2 * SLAB];
__device__ float g_c2[SLAB];

// ---------------------------------------------------------------------------
// Fused conv + LSTM-gate step kernel.
// Block: (tile = blockIdx.x in [0,8), batch b = blockIdx.y).
// Computes, for 16 hidden channels (hc0 = tile*16), all 4 gate pre-activations
// over the full 15x15 image, then does the LSTM update in-register.
// Input channels: [0, CIN_X) from xin, [CIN_X, CIN_X+128) from hin.
// Local output-channel layout: o = j*4 + gate (j in 0..15), global
// oc = gate*128 + hc0 + j   (gates stacked i,f,o,g as in jnp.split).
// ---------------------------------------------------------------------------
template<int CIN_X>
__global__ __launch_bounds__(256, 2)
void convlstm_step_kernel(const float* __restrict__ xin, long xin_bstride,
                          const float* __restrict__ hin,
                          const float* __restrict__ Wt,
                          const float* __restrict__ bias,
                          float* __restrict__ cst,
                          float* __restrict__ hout)
{
    constexpr int CTOT = CIN_X + HID;
    constexpr int CH   = 8;            // channels per smem chunk

    __shared__ float s_in[CH][SH][SH];         // 8*17*17*4  = 9248 B
    __shared__ float s_w[CH * 9 * 64];         // 8*9*64*4   = 18432 B

    const int tile = blockIdx.x;               // 0..7
    const int b    = blockIdx.y;               // 0..63
    const int hc0  = tile * 16;
    const int tid  = threadIdx.x;
    const int tp   = tid & 31;                 // pixel lane
    const int tc   = tid >> 5;                 // oc group (0..7): ocs tc*8 .. tc*8+7

    // Thread pixel set: p = tp + 32*r, r = 0..7
    int  offs[8];
    bool pok[8];
    #pragma unroll
    for (int r = 0; r < 8; r++) {
        int p  = tp + 32 * r;
        pok[r] = (p < PIX);
        int pc = pok[r] ? p : 0;
        int py = pc / 15, px = pc % 15;
        offs[r] = py * SH + px;                // top-left of 3x3 window in padded tile
    }

    float acc[8][8];
    #pragma unroll
    for (int r = 0; r < 8; r++)
        #pragma unroll
        for (int o = 0; o < 8; o++) acc[r][o] = 0.f;

    for (int c0 = 0; c0 < CTOT; c0 += CH) {
        // ---- stage input chunk (zero-padded halo) ----
        const bool from_x = (c0 < CIN_X);
        const float* base = from_x
            ? (xin + (long)b * xin_bstride + (long)c0 * PIX)
            : (hin + ((long)b * HID + (c0 - CIN_X)) * PIX);

        for (int i = tid; i < CH * SH * SH; i += 256) {
            int c  = i / (SH * SH);
            int r2 = i % (SH * SH);
            int yy = r2 / SH, xx = r2 % SH;
            float v = 0.f;
            if (yy >= 1 && yy <= 15 && xx >= 1 && xx <= 15)
                v = base[c * PIX + (yy - 1) * 15 + (xx - 1)];
            s_in[c][yy][xx] = v;
        }
        // ---- stage weight chunk: s_w[(c*9+k)*64 + o], o = j*4+gate ----
        for (int i = tid; i < CH * 9 * 64; i += 256) {
            int o  = i & 63;
            int ck = i >> 6;
            int c  = ck / 9, k = ck % 9;
            int j = o >> 2, gate = o & 3;
            int ocg = gate * HID + hc0 + j;
            s_w[i] = Wt[((long)ocg * CTOT + (c0 + c)) * 9 + k];
        }
        __syncthreads();

        #pragma unroll 1
        for (int c = 0; c < CH; c++) {
            const float* sp = &s_in[c][0][0];
            #pragma unroll
            for (int k = 0; k < 9; k++) {
                const int dy = k / 3, dx = k % 3;
                const float4 w0 = *(const float4*)&s_w[(c * 9 + k) * 64 + tc * 8];
                const float4 w1 = *(const float4*)&s_w[(c * 9 + k) * 64 + tc * 8 + 4];
                #pragma unroll
                for (int r = 0; r < 8; r++) {
                    float a = sp[offs[r] + dy * SH + dx];
                    acc[r][0] += a * w0.x;
                    acc[r][1] += a * w0.y;
                    acc[r][2] += a * w0.z;
                    acc[r][3] += a * w0.w;
                    acc[r][4] += a * w1.x;
                    acc[r][5] += a * w1.y;
                    acc[r][6] += a * w1.z;
                    acc[r][7] += a * w1.w;
                }
            }
        }
        __syncthreads();
    }

    // ---- fused LSTM gate epilogue ----
    // Thread's oc o = tc*8+oi  ->  j = tc*2 + (oi>>2), gate = oi&3
    #pragma unroll
    for (int j2 = 0; j2 < 2; j2++) {
        const int   hc = hc0 + tc * 2 + j2;
        const float bi = bias[0 * HID + hc];
        const float bf = bias[1 * HID + hc];
        const float bo = bias[2 * HID + hc];
        const float bg = bias[3 * HID + hc];
        #pragma unroll
        for (int r = 0; r < 8; r++) {
            if (!pok[r]) continue;
            const int p = tp + 32 * r;
            float zi = acc[r][j2 * 4 + 0] + bi;
            float zf = acc[r][j2 * 4 + 1] + bf;
            float zo = acc[r][j2 * 4 + 2] + bo;
            float zg = acc[r][j2 * 4 + 3] + bg;
            float ig = 1.f / (1.f + expf(-zi));
            float fg = 1.f / (1.f + expf(-zf));
            float og = 1.f / (1.f + expf(-zo));
            float gg = tanhf(zg);
            long idx = ((long)b * HID + hc) * PIX + p;
            float cn = fg * cst[idx] + ig * gg;
            cst[idx]  = cn;
            hout[idx] = og * tanhf(cn);
        }
    }
}

// ---------------------------------------------------------------------------
// Final dense: out[b, o] = sum_k h2[b, k] * Wd[k, o] + bd[o]
// k = hc*225 + p  (matches reshape of [HID, H, W] row-major).
// ---------------------------------------------------------------------------
__global__ __launch_bounds__(128)
void dense_kernel(const float* __restrict__ feat,
                  const float* __restrict__ Wd,
                  const float* __restrict__ bd,
                  float* __restrict__ out)
{
    __shared__ float sf[1024];
    const int b = blockIdx.x;
    const int o = threadIdx.x;
    const float* f = feat + (long)b * (HID * PIX);

    float s0 = 0.f, s1 = 0.f, s2 = 0.f, s3 = 0.f;
    const int KTOT = HID * PIX;                 // 28800
    for (int k0 = 0; k0 < KTOT; k0 += 1024) {
        __syncthreads();
        for (int i = o; i < 1024; i += 128) {
            int k = k0 + i;
            sf[i] = (k < KTOT) ? f[k] : 0.f;
        }
        __syncthreads();
        int kmax = min(1024, KTOT - k0);
        for (int kk = 0; kk < kmax; kk += 4) {
            s0 += sf[kk + 0] * Wd[(long)(k0 + kk + 0) * 128 + o];
            s1 += sf[kk + 1] * Wd[(long)(k0 + kk + 1) * 128 + o];
            s2 += sf[kk + 2] * Wd[(long)(k0 + kk + 2) * 128 + o];
            s3 += sf[kk + 3] * Wd[(long)(k0 + kk + 3) * 128 + o];
        }
    }
    out[b * 128 + o] = (s0 + s1) + (s2 + s3) + bd[o];
}

// ---------------------------------------------------------------------------
extern "C" void kernel_launch(void* const* d_in, const int* in_sizes, int n_in,
                              void* d_out, int out_size)
{
    const float* enc = (const float*)d_in[0];  // [B, T, 64, 15, 15]
    const float* W0  = (const float*)d_in[1];  // [512, 192, 3, 3]
    const float* b0  = (const float*)d_in[2];  // [512]
    const float* W1  = (const float*)d_in[3];  // [512, 256, 3, 3]
    const float* b1  = (const float*)d_in[4];  // [512]
    const float* Wd  = (const float*)d_in[5];  // [28800, 128]
    const float* bd  = (const float*)d_in[6];  // [128]
    float* out = (float*)d_out;                // [64, 128]

    float *h1, *c1, *h2, *c2;
    cudaGetSymbolAddress((void**)&h1, g_h1);
    cudaGetSymbolAddress((void**)&c1, g_c1);
    cudaGetSymbolAddress((void**)&h2, g_h2);
    cudaGetSymbolAddress((void**)&c2, g_c2);

    // Zero initial state (ping-0 of h buffers + cell states)
    cudaMemsetAsync(h1, 0, sizeof(float) * SLAB, 0);
    cudaMemsetAsync(c1, 0, sizeof(float) * SLAB, 0);
    cudaMemsetAsync(h2, 0, sizeof(float) * SLAB, 0);
    cudaMemsetAsync(c2, 0, sizeof(float) * SLAB, 0);

    dim3 grid(8, BATCH);
    const long enc_bstride = (long)TT * C_IN * PIX;   // per-batch stride in encoder_output
    const long h_bstride   = (long)HID * PIX;

    for (int t = 0; t < TT; t++) {
        const int rd = t & 1, wr = rd ^ 1;
        // Layer 0: x = encoder_output[:, t], h = h1[rd] -> h1[wr]
        convlstm_step_kernel<C_IN><<<grid, 256>>>(
            enc + (long)t * C_IN * PIX, enc_bstride,
            h1 + (long)rd * SLAB, W0, b0, c1, h1 + (long)wr * SLAB);
        // Layer 1: x = h1[wr] (fresh), h = h2[rd] -> h2[wr]
        convlstm_step_kernel<HID><<<grid, 256>>>(
            h1 + (long)wr * SLAB, h_bstride,
            h2 + (long)rd * SLAB, W1, b1, c2, h2 + (long)wr * SLAB);
    }
    // After t = 47, fresh h2 lives in ping 0 (wr = (47&1)^1 = 0).
    dense_kernel<<<BATCH, 128>>>(h2, Wd, bd, out);
}